// round 1
// baseline (speedup 1.0000x reference)
#include <cuda_runtime.h>
#include <math.h>

namespace {
constexpr int kB = 32, kC = 192, kH = 56, kW = 56;
constexpr int kHeads = 6, kD = 32, kWS = 7, kShift = 3, kHid = 768;
constexpr int kNWin = kB * 8 * 8;   // 2048 windows
constexpr int kTok = kWS * kWS;     // 49
constexpr int kNT = kNWin * kTok;   // 100352 tokens
constexpr int kHWp = kH * kW;       // 3136
}

// ---------------- scratch (static __device__, allocation-free) ----------------
__device__ float g_wt1[kC * 9 * kHid];          // conv1 weights transposed [(c*9+t), o]
__device__ float g_wt2[kHid * 9 * kC];          // conv2 weights transposed
__device__ float g_xw[(size_t)kNT * kC];        // LN1 output, window layout [win][tok][c]
__device__ float g_q [(size_t)kNT * kC];        // q [win][head][tok][d]
__device__ float g_kk[(size_t)kNT * kC];        // k
__device__ float g_vv[(size_t)kNT * kC];        // v
__device__ float g_ao[(size_t)kNT * kC];        // attention out [win][tok][c]
__device__ float g_x1[(size_t)kNT * kC];        // x + attn branch (NCHW)
__device__ float g_h0[(size_t)kNT * kC];        // LN2 out (NCHW)
__device__ float g_h1[(size_t)kNT * kHid];      // conv1+gelu out (NCHW, 768ch)

// ---------------- weight transpose:  w[o][c][t] -> wt[(c*9+t)*OC + o] --------
template<int PH>
__global__ void wtrans_kernel(const float* __restrict__ w) {
    constexpr int OC = (PH == 0) ? kHid : kC;
    constexpr int IC = (PH == 0) ? kC : kHid;
    float* wt = (PH == 0) ? g_wt1 : g_wt2;
    int i = blockIdx.x * 256 + threadIdx.x;
    if (i < OC * IC * 9) {
        int o = i / (IC * 9);
        int ct = i - o * (IC * 9);
        wt[(size_t)ct * OC + o] = w[i];
    }
}

// ---------------- LayerNorm over C; MODE 0: x -> g_xw (roll + window) --------
// ----------------                    MODE 1: g_x1 -> g_h0 (plain NCHW) -------
template<int MODE>
__global__ void ln_kernel(const float* __restrict__ xin,
                          const float* __restrict__ gam,
                          const float* __restrict__ bet) {
    int p = blockIdx.x * 256 + threadIdx.x;
    if (p >= kNT) return;
    const float* src = (MODE == 0) ? xin : g_x1;
    int b = p / kHWp;
    int rem = p - b * kHWp;
    int hp = rem / kW, wp = rem - (rem / kW) * kW;
    int h = hp, w = wp;
    if (MODE == 0) {  // rolled frame pixel hp reads source (hp+shift) mod H
        h = hp + kShift; if (h >= kH) h -= kH;
        w = wp + kShift; if (w >= kW) w -= kW;
    }
    const float* xp = src + ((size_t)b * kC) * kHWp + h * kW + w;
    float s = 0.f, s2 = 0.f;
#pragma unroll 4
    for (int c = 0; c < kC; c++) { float v = xp[(size_t)c * kHWp]; s += v; s2 += v * v; }
    float m = s * (1.f / kC);
    float var = s2 * (1.f / kC) - m * m;
    float rs = rsqrtf(var + 1e-5f);
    if (MODE == 0) {
        int win = b * 64 + (hp / 7) * 8 + (wp / 7);
        int tok = (hp % 7) * 7 + (wp % 7);
        float* op = g_xw + ((size_t)win * kTok + tok) * kC;
#pragma unroll 4
        for (int c = 0; c < kC; c++)
            op[c] = (xp[(size_t)c * kHWp] - m) * rs * gam[c] + bet[c];
    } else {
        float* op = g_h0 + ((size_t)b * kC) * kHWp + h * kW + w;
#pragma unroll 4
        for (int c = 0; c < kC; c++)
            op[(size_t)c * kHWp] = (xp[(size_t)c * kHWp] - m) * rs * gam[c] + bet[c];
    }
}

// ---------------- QKV GEMM: [kNT,192] x [576,192]^T, scatter to q/k/v -------
__global__ __launch_bounds__(256) void gemm_qkv_kernel(const float* __restrict__ Wm,
                                                       const float* __restrict__ bias) {
    __shared__ float sA[16][132];
    __shared__ float sW[16][64];
    const int tid = threadIdx.x;
    const int tn = tid & 31, tm = tid >> 5;
    const int nb = blockIdx.x * 128;
    const int mb = blockIdx.y * 64;
    float acc[8][4];
#pragma unroll
    for (int i = 0; i < 8; i++)
#pragma unroll
        for (int j = 0; j < 4; j++) acc[i][j] = 0.f;
    const int nl = tid >> 1, kh = (tid & 1) * 8;
    const int ml = tid >> 2, kq = (tid & 3) * 4;
    const float* Ap = g_xw + (size_t)(nb + nl) * kC + kh;
    const float* Wp = Wm + (size_t)(mb + ml) * kC + kq;
    for (int k0 = 0; k0 < kC; k0 += 16) {
        float4 a0 = *(const float4*)(Ap + k0);
        float4 a1 = *(const float4*)(Ap + k0 + 4);
        float4 w0 = *(const float4*)(Wp + k0);
        sA[kh + 0][nl] = a0.x; sA[kh + 1][nl] = a0.y; sA[kh + 2][nl] = a0.z; sA[kh + 3][nl] = a0.w;
        sA[kh + 4][nl] = a1.x; sA[kh + 5][nl] = a1.y; sA[kh + 6][nl] = a1.z; sA[kh + 7][nl] = a1.w;
        sW[kq + 0][ml] = w0.x; sW[kq + 1][ml] = w0.y; sW[kq + 2][ml] = w0.z; sW[kq + 3][ml] = w0.w;
        __syncthreads();
#pragma unroll
        for (int k = 0; k < 16; k++) {
            float4 av  = *(const float4*)&sA[k][tn * 4];
            float4 wv0 = *(const float4*)&sW[k][tm * 8];
            float4 wv1 = *(const float4*)&sW[k][tm * 8 + 4];
            float a[4] = {av.x, av.y, av.z, av.w};
            float w[8] = {wv0.x, wv0.y, wv0.z, wv0.w, wv1.x, wv1.y, wv1.z, wv1.w};
#pragma unroll
            for (int mi = 0; mi < 8; mi++)
#pragma unroll
                for (int nj = 0; nj < 4; nj++) acc[mi][nj] += w[mi] * a[nj];
        }
        __syncthreads();
    }
#pragma unroll
    for (int nj = 0; nj < 4; nj++) {
        int n = nb + tn * 4 + nj;
        int win = n / 49, tok = n - win * 49;
#pragma unroll
        for (int mi = 0; mi < 8; mi++) {
            int m = mb + tm * 8 + mi;
            float val = acc[mi][nj] + bias[m];
            int sec = m / kC;
            int c = m - sec * kC;
            float* dst = (sec == 0) ? g_q : (sec == 1) ? g_kk : g_vv;
            dst[((size_t)(win * kHeads + (c >> 5)) * kTok + tok) * kD + (c & 31)] = val;
        }
    }
}

// ---------------- attention: one block per (window, head) --------------------
__global__ __launch_bounds__(64) void attn_kernel() {
    const int wh = blockIdx.x;  // win*6 + head
    __shared__ float sq[kTok * kD], sk[kTok * kD], sv[kTok * kD];
    __shared__ float ss[kTok][64];
    const size_t base = (size_t)wh * kTok * kD;
    for (int i = threadIdx.x; i < kTok * kD; i += 64) {
        sq[i] = g_q[base + i]; sk[i] = g_kk[base + i]; sv[i] = g_vv[base + i];
    }
    __syncthreads();
    int r = threadIdx.x;
    if (r < kTok) {
        float qr[kD];
#pragma unroll
        for (int d = 0; d < kD; d++) qr[d] = sq[r * kD + d];
        float mx = -1e30f;
        for (int mrow = 0; mrow < kTok; mrow++) {
            float dot = 0.f;
#pragma unroll
            for (int d = 0; d < kD; d++) dot += qr[d] * sk[mrow * kD + d];
            dot *= 0.17677669529663689f;   // 32^-0.5
            ss[mrow][r] = dot;
            mx = fmaxf(mx, dot);
        }
        float sum = 0.f;
        for (int mrow = 0; mrow < kTok; mrow++) {
            float e = __expf(ss[mrow][r] - mx);
            ss[mrow][r] = e; sum += e;
        }
        float inv = 1.f / sum;
        int win = wh / kHeads, head = wh - win * kHeads;
        float* op = g_ao + ((size_t)win * kTok + r) * kC + head * kD;
#pragma unroll 4
        for (int d = 0; d < kD; d++) {
            float a = 0.f;
            for (int mrow = 0; mrow < kTok; mrow++) a += ss[mrow][r] * sv[mrow * kD + d];
            op[d] = a * inv;
        }
    }
}

// ---------------- proj GEMM + inverse roll + residual -> g_x1 ----------------
__global__ __launch_bounds__(256) void gemm_proj_kernel(const float* __restrict__ Wm,
                                                        const float* __restrict__ bias,
                                                        const float* __restrict__ xin) {
    __shared__ float sA[16][132];
    __shared__ float sW[16][64];
    const int tid = threadIdx.x;
    const int tn = tid & 31, tm = tid >> 5;
    const int nb = blockIdx.x * 128;
    const int mb = blockIdx.y * 64;
    float acc[8][4];
#pragma unroll
    for (int i = 0; i < 8; i++)
#pragma unroll
        for (int j = 0; j < 4; j++) acc[i][j] = 0.f;
    const int nl = tid >> 1, kh = (tid & 1) * 8;
    const int ml = tid >> 2, kq = (tid & 3) * 4;
    const float* Ap = g_ao + (size_t)(nb + nl) * kC + kh;
    const float* Wp = Wm + (size_t)(mb + ml) * kC + kq;
    for (int k0 = 0; k0 < kC; k0 += 16) {
        float4 a0 = *(const float4*)(Ap + k0);
        float4 a1 = *(const float4*)(Ap + k0 + 4);
        float4 w0 = *(const float4*)(Wp + k0);
        sA[kh + 0][nl] = a0.x; sA[kh + 1][nl] = a0.y; sA[kh + 2][nl] = a0.z; sA[kh + 3][nl] = a0.w;
        sA[kh + 4][nl] = a1.x; sA[kh + 5][nl] = a1.y; sA[kh + 6][nl] = a1.z; sA[kh + 7][nl] = a1.w;
        sW[kq + 0][ml] = w0.x; sW[kq + 1][ml] = w0.y; sW[kq + 2][ml] = w0.z; sW[kq + 3][ml] = w0.w;
        __syncthreads();
#pragma unroll
        for (int k = 0; k < 16; k++) {
            float4 av  = *(const float4*)&sA[k][tn * 4];
            float4 wv0 = *(const float4*)&sW[k][tm * 8];
            float4 wv1 = *(const float4*)&sW[k][tm * 8 + 4];
            float a[4] = {av.x, av.y, av.z, av.w};
            float w[8] = {wv0.x, wv0.y, wv0.z, wv0.w, wv1.x, wv1.y, wv1.z, wv1.w};
#pragma unroll
            for (int mi = 0; mi < 8; mi++)
#pragma unroll
                for (int nj = 0; nj < 4; nj++) acc[mi][nj] += w[mi] * a[nj];
        }
        __syncthreads();
    }
#pragma unroll
    for (int nj = 0; nj < 4; nj++) {
        int n = nb + tn * 4 + nj;
        int win = n / 49, tok = n - win * 49;
        int bb  = win >> 6;
        int whh = (win >> 3) & 7;
        int www = win & 7;
        int ti = tok / 7, tj = tok - ti * 7;
        int hi = whh * 7 + ti + kShift; if (hi >= kH) hi -= kH;
        int wi = www * 7 + tj + kShift; if (wi >= kW) wi -= kW;
#pragma unroll
        for (int mi = 0; mi < 8; mi++) {
            int m = mb + tm * 8 + mi;   // output channel
            float val = acc[mi][nj] + bias[m];
            size_t idx = ((size_t)(bb * kC + m) * kH + hi) * kW + wi;
            g_x1[idx] = xin[idx] + val;
        }
    }
}

// ---------------- 3x3 conv, implicit GEMM; PH0: h0->h1 (+gelu), PH1: h1->out (+resid)
template<int PH>
__global__ __launch_bounds__(128) void conv3x3_kernel(const float* __restrict__ bias,
                                                      float* __restrict__ outp) {
    constexpr int IC = (PH == 0) ? kC : kHid;
    constexpr int OC = (PH == 0) ? kHid : kC;
    constexpr int KC = 8;
    const float* in = (PH == 0) ? g_h0 : g_h1;
    const float* wt = (PH == 0) ? g_wt1 : g_wt2;
    float* out = (PH == 0) ? g_h1 : outp;

    const int b = blockIdx.z;
    const int ob = blockIdx.y * 64;
    const int rt = blockIdx.x >> 2, ct = blockIdx.x & 3;
    const int r0 = rt * 8, c0col = ct * 16;
    const int tid = threadIdx.x;
    const int tp = tid & 15, to = tid >> 4;   // to: 8 o-positions; tp: 16 pixel groups
    const int rr = tp >> 1, cg = tp & 1;      // row 0..7, colgroup 0..1 (8 px each)

    __shared__ float sx[KC][10][19];
    __shared__ float sw[KC * 9 * 64];

    float acc[8][8];
#pragma unroll
    for (int i = 0; i < 8; i++)
#pragma unroll
        for (int j = 0; j < 8; j++) acc[i][j] = 0.f;

    for (int c0 = 0; c0 < IC; c0 += KC) {
        __syncthreads();
        // input patch KC x 10 x 18 (with halo, zero SAME padding)
        for (int i = tid; i < KC * 180; i += 128) {
            int c = i / 180, rem2 = i - c * 180;
            int y = rem2 / 18, xcol = rem2 - y * 18;
            int gy = r0 + y - 1, gx = c0col + xcol - 1;
            float v = 0.f;
            if (gy >= 0 && gy < kH && gx >= 0 && gx < kW)
                v = in[((size_t)(b * IC + c0 + c) * kH + gy) * kW + gx];
            sx[c][y][xcol] = v;
        }
        // weights KC x 9 x 64 (already transposed: [(c*9+t), o] -> fully coalesced)
        const float* wp = wt + (size_t)c0 * 9 * OC + ob;
#pragma unroll 4
        for (int i = tid; i < KC * 9 * 64; i += 128) {
            int ct9 = i >> 6, o = i & 63;
            sw[i] = wp[(size_t)ct9 * OC + o];
        }
        __syncthreads();
#pragma unroll 1
        for (int c = 0; c < KC; c++) {
#pragma unroll
            for (int dy = 0; dy < 3; dy++) {
                float xr[10];
#pragma unroll
                for (int j = 0; j < 10; j++) xr[j] = sx[c][rr + dy][cg * 8 + j];
#pragma unroll
                for (int dx = 0; dx < 3; dx++) {
                    const float4 wv0 = *(const float4*)&sw[(c * 9 + dy * 3 + dx) * 64 + to * 8];
                    const float4 wv1 = *(const float4*)&sw[(c * 9 + dy * 3 + dx) * 64 + to * 8 + 4];
                    float wv[8] = {wv0.x, wv0.y, wv0.z, wv0.w, wv1.x, wv1.y, wv1.z, wv1.w};
#pragma unroll
                    for (int i = 0; i < 8; i++)
#pragma unroll
                        for (int j = 0; j < 8; j++)
                            acc[i][j] += wv[i] * xr[j + dx];
                }
            }
        }
    }
    const int gy = r0 + rr;  // rows always < 56
#pragma unroll
    for (int i = 0; i < 8; i++) {
        const int o = ob + to * 8 + i;
        const float bv = bias[o];
#pragma unroll
        for (int j = 0; j < 8; j++) {
            const int gx = c0col + cg * 8 + j;
            if (gx < kW) {
                const size_t idx = ((size_t)(b * OC + o) * kH + gy) * kW + gx;
                float v = acc[i][j] + bv;
                if (PH == 0) {
                    out[idx] = 0.5f * v * (1.f + erff(v * 0.70710678118654752f));  // exact gelu
                } else {
                    out[idx] = v + g_x1[idx];
                }
            }
        }
    }
}

// ---------------- launch -----------------------------------------------------
extern "C" void kernel_launch(void* const* d_in, const int* in_sizes, int n_in,
                              void* d_out, int out_size) {
    (void)in_sizes; (void)n_in; (void)out_size;
    const float* x       = (const float*)d_in[0];
    const float* ln1_g   = (const float*)d_in[1];
    const float* ln1_b   = (const float*)d_in[2];
    const float* qkv_w   = (const float*)d_in[3];
    const float* qkv_b   = (const float*)d_in[4];
    const float* proj_w  = (const float*)d_in[5];
    const float* proj_b  = (const float*)d_in[6];
    const float* ln2_g   = (const float*)d_in[7];
    const float* ln2_b   = (const float*)d_in[8];
    const float* conv1_w = (const float*)d_in[9];
    const float* conv1_b = (const float*)d_in[10];
    const float* conv2_w = (const float*)d_in[11];
    const float* conv2_b = (const float*)d_in[12];
    float* out = (float*)d_out;

    wtrans_kernel<0><<<(kHid * kC * 9 + 255) / 256, 256>>>(conv1_w);
    wtrans_kernel<1><<<(kC * kHid * 9 + 255) / 256, 256>>>(conv2_w);

    ln_kernel<0><<<kNT / 256, 256>>>(x, ln1_g, ln1_b);
    gemm_qkv_kernel<<<dim3(kNT / 128, (3 * kC) / 64), 256>>>(qkv_w, qkv_b);
    attn_kernel<<<kNWin * kHeads, 64>>>();
    gemm_proj_kernel<<<dim3(kNT / 128, kC / 64), 256>>>(proj_w, proj_b, x);
    ln_kernel<1><<<kNT / 256, 256>>>(nullptr, ln2_g, ln2_b);
    conv3x3_kernel<0><<<dim3(28, kHid / 64, kB), 128>>>(conv1_b, nullptr);
    conv3x3_kernel<1><<<dim3(28, kC / 64, kB), 128>>>(conv2_b, out);
}

// round 2
// speedup vs baseline: 1.7838x; 1.7838x over previous
#include <cuda_runtime.h>
#include <math.h>

namespace {
constexpr int kB = 32, kC = 192, kH = 56, kW = 56;
constexpr int kHeads = 6, kD = 32, kWS = 7, kShift = 3, kHid = 768;
constexpr int kNWin = kB * 8 * 8;   // 2048 windows
constexpr int kTok = kWS * kWS;     // 49
constexpr int kNT = kNWin * kTok;   // 100352 tokens
constexpr int kHWp = kH * kW;       // 3136
}

// ---------------- scratch (static __device__, allocation-free) ----------------
__device__ float g_wt1[kC * 9 * kHid];          // conv1 weights transposed [(c*9+t), o]
__device__ float g_wt2[kHid * 9 * kC];          // conv2 weights transposed
__device__ float g_xw[(size_t)kNT * kC];        // LN1 output, window layout [win][tok][c]
__device__ float g_q [(size_t)kNT * kC];        // q [win][head][tok][d]
__device__ float g_kk[(size_t)kNT * kC];        // k
__device__ float g_vv[(size_t)kNT * kC];        // v
__device__ float g_ao[(size_t)kNT * kC];        // attention out [win][tok][c]
__device__ float g_x1[(size_t)kNT * kC];        // x + attn branch (NCHW)
__device__ float g_h0[(size_t)kNT * kC];        // LN2 out (NCHW)
__device__ float g_h1[(size_t)kNT * kHid];      // conv1+gelu out (NCHW, 768ch)

// ---------------- helpers ----------------------------------------------------
__device__ __forceinline__ unsigned f2tf32(float x) {
    unsigned r; asm("cvt.rna.tf32.f32 %0, %1;" : "=r"(r) : "f"(x)); return r;
}
__device__ __forceinline__ void mma_tf32(float* d, const unsigned* a, const unsigned* b) {
    asm volatile(
        "mma.sync.aligned.m16n8k8.row.col.f32.tf32.tf32.f32 "
        "{%0,%1,%2,%3}, {%4,%5,%6,%7}, {%8,%9}, {%0,%1,%2,%3};\n"
        : "+f"(d[0]), "+f"(d[1]), "+f"(d[2]), "+f"(d[3])
        : "r"(a[0]), "r"(a[1]), "r"(a[2]), "r"(a[3]), "r"(b[0]), "r"(b[1]));
}

// ---------------- weight transpose:  w[o][c][t] -> wt[(c*9+t)*OC + o] --------
template<int PH>
__global__ void wtrans_kernel(const float* __restrict__ w) {
    constexpr int OC = (PH == 0) ? kHid : kC;
    constexpr int IC = (PH == 0) ? kC : kHid;
    float* wt = (PH == 0) ? g_wt1 : g_wt2;
    int i = blockIdx.x * 256 + threadIdx.x;
    if (i < OC * IC * 9) {
        int o = i / (IC * 9);
        int ct = i - o * (IC * 9);
        wt[(size_t)ct * OC + o] = w[i];
    }
}

// ---------------- LayerNorm over C; MODE 0: x -> g_xw (roll + window) --------
// ----------------                    MODE 1: g_x1 -> g_h0 (plain NCHW) -------
template<int MODE>
__global__ void ln_kernel(const float* __restrict__ xin,
                          const float* __restrict__ gam,
                          const float* __restrict__ bet) {
    int p = blockIdx.x * 256 + threadIdx.x;
    if (p >= kNT) return;
    const float* src = (MODE == 0) ? xin : g_x1;
    int b = p / kHWp;
    int rem = p - b * kHWp;
    int hp = rem / kW, wp = rem - (rem / kW) * kW;
    int h = hp, w = wp;
    if (MODE == 0) {  // rolled frame pixel hp reads source (hp+shift) mod H
        h = hp + kShift; if (h >= kH) h -= kH;
        w = wp + kShift; if (w >= kW) w -= kW;
    }
    const float* xp = src + ((size_t)b * kC) * kHWp + h * kW + w;
    float s = 0.f, s2 = 0.f;
#pragma unroll 4
    for (int c = 0; c < kC; c++) { float v = xp[(size_t)c * kHWp]; s += v; s2 += v * v; }
    float m = s * (1.f / kC);
    float var = s2 * (1.f / kC) - m * m;
    float rs = rsqrtf(var + 1e-5f);
    if (MODE == 0) {
        int win = b * 64 + (hp / 7) * 8 + (wp / 7);
        int tok = (hp % 7) * 7 + (wp % 7);
        float* op = g_xw + ((size_t)win * kTok + tok) * kC;
#pragma unroll 4
        for (int c = 0; c < kC; c++)
            op[c] = (xp[(size_t)c * kHWp] - m) * rs * gam[c] + bet[c];
    } else {
        float* op = g_h0 + ((size_t)b * kC) * kHWp + h * kW + w;
#pragma unroll 4
        for (int c = 0; c < kC; c++)
            op[(size_t)c * kHWp] = (xp[(size_t)c * kHWp] - m) * rs * gam[c] + bet[c];
    }
}

// ---------------- QKV GEMM: [kNT,192] x [576,192]^T, scatter to q/k/v -------
__global__ __launch_bounds__(256) void gemm_qkv_kernel(const float* __restrict__ Wm,
                                                       const float* __restrict__ bias) {
    __shared__ float sA[16][132];
    __shared__ float sW[16][64];
    const int tid = threadIdx.x;
    const int tn = tid & 31, tm = tid >> 5;
    const int nb = blockIdx.x * 128;
    const int mb = blockIdx.y * 64;
    float acc[8][4];
#pragma unroll
    for (int i = 0; i < 8; i++)
#pragma unroll
        for (int j = 0; j < 4; j++) acc[i][j] = 0.f;
    const int nl = tid >> 1, kh = (tid & 1) * 8;
    const int ml = tid >> 2, kq = (tid & 3) * 4;
    const float* Ap = g_xw + (size_t)(nb + nl) * kC + kh;
    const float* Wp = Wm + (size_t)(mb + ml) * kC + kq;
    for (int k0 = 0; k0 < kC; k0 += 16) {
        float4 a0 = *(const float4*)(Ap + k0);
        float4 a1 = *(const float4*)(Ap + k0 + 4);
        float4 w0 = *(const float4*)(Wp + k0);
        sA[kh + 0][nl] = a0.x; sA[kh + 1][nl] = a0.y; sA[kh + 2][nl] = a0.z; sA[kh + 3][nl] = a0.w;
        sA[kh + 4][nl] = a1.x; sA[kh + 5][nl] = a1.y; sA[kh + 6][nl] = a1.z; sA[kh + 7][nl] = a1.w;
        sW[kq + 0][ml] = w0.x; sW[kq + 1][ml] = w0.y; sW[kq + 2][ml] = w0.z; sW[kq + 3][ml] = w0.w;
        __syncthreads();
#pragma unroll
        for (int k = 0; k < 16; k++) {
            float4 av  = *(const float4*)&sA[k][tn * 4];
            float4 wv0 = *(const float4*)&sW[k][tm * 8];
            float4 wv1 = *(const float4*)&sW[k][tm * 8 + 4];
            float a[4] = {av.x, av.y, av.z, av.w};
            float w[8] = {wv0.x, wv0.y, wv0.z, wv0.w, wv1.x, wv1.y, wv1.z, wv1.w};
#pragma unroll
            for (int mi = 0; mi < 8; mi++)
#pragma unroll
                for (int nj = 0; nj < 4; nj++) acc[mi][nj] += w[mi] * a[nj];
        }
        __syncthreads();
    }
#pragma unroll
    for (int nj = 0; nj < 4; nj++) {
        int n = nb + tn * 4 + nj;
        int win = n / 49, tok = n - win * 49;
#pragma unroll
        for (int mi = 0; mi < 8; mi++) {
            int m = mb + tm * 8 + mi;
            float val = acc[mi][nj] + bias[m];
            int sec = m / kC;
            int c = m - sec * kC;
            float* dst = (sec == 0) ? g_q : (sec == 1) ? g_kk : g_vv;
            dst[((size_t)(win * kHeads + (c >> 5)) * kTok + tok) * kD + (c & 31)] = val;
        }
    }
}

// ---------------- attention: one block per (window, head) --------------------
__global__ __launch_bounds__(64) void attn_kernel() {
    const int wh = blockIdx.x;  // win*6 + head
    __shared__ float sq[kTok * kD], sk[kTok * kD], sv[kTok * kD];
    __shared__ float ss[kTok][64];
    const size_t base = (size_t)wh * kTok * kD;
    for (int i = threadIdx.x; i < kTok * kD; i += 64) {
        sq[i] = g_q[base + i]; sk[i] = g_kk[base + i]; sv[i] = g_vv[base + i];
    }
    __syncthreads();
    int r = threadIdx.x;
    if (r < kTok) {
        float qr[kD];
#pragma unroll
        for (int d = 0; d < kD; d++) qr[d] = sq[r * kD + d];
        float mx = -1e30f;
        for (int mrow = 0; mrow < kTok; mrow++) {
            float dot = 0.f;
#pragma unroll
            for (int d = 0; d < kD; d++) dot += qr[d] * sk[mrow * kD + d];
            dot *= 0.17677669529663689f;   // 32^-0.5
            ss[mrow][r] = dot;
            mx = fmaxf(mx, dot);
        }
        float sum = 0.f;
        for (int mrow = 0; mrow < kTok; mrow++) {
            float e = __expf(ss[mrow][r] - mx);
            ss[mrow][r] = e; sum += e;
        }
        float inv = 1.f / sum;
        int win = wh / kHeads, head = wh - win * kHeads;
        float* op = g_ao + ((size_t)win * kTok + r) * kC + head * kD;
#pragma unroll 4
        for (int d = 0; d < kD; d++) {
            float a = 0.f;
            for (int mrow = 0; mrow < kTok; mrow++) a += ss[mrow][r] * sv[mrow * kD + d];
            op[d] = a * inv;
        }
    }
}

// ---------------- proj GEMM + inverse roll + residual -> g_x1 ----------------
__global__ __launch_bounds__(256) void gemm_proj_kernel(const float* __restrict__ Wm,
                                                        const float* __restrict__ bias,
                                                        const float* __restrict__ xin) {
    __shared__ float sA[16][132];
    __shared__ float sW[16][64];
    const int tid = threadIdx.x;
    const int tn = tid & 31, tm = tid >> 5;
    const int nb = blockIdx.x * 128;
    const int mb = blockIdx.y * 64;
    float acc[8][4];
#pragma unroll
    for (int i = 0; i < 8; i++)
#pragma unroll
        for (int j = 0; j < 4; j++) acc[i][j] = 0.f;
    const int nl = tid >> 1, kh = (tid & 1) * 8;
    const int ml = tid >> 2, kq = (tid & 3) * 4;
    const float* Ap = g_ao + (size_t)(nb + nl) * kC + kh;
    const float* Wp = Wm + (size_t)(mb + ml) * kC + kq;
    for (int k0 = 0; k0 < kC; k0 += 16) {
        float4 a0 = *(const float4*)(Ap + k0);
        float4 a1 = *(const float4*)(Ap + k0 + 4);
        float4 w0 = *(const float4*)(Wp + k0);
        sA[kh + 0][nl] = a0.x; sA[kh + 1][nl] = a0.y; sA[kh + 2][nl] = a0.z; sA[kh + 3][nl] = a0.w;
        sA[kh + 4][nl] = a1.x; sA[kh + 5][nl] = a1.y; sA[kh + 6][nl] = a1.z; sA[kh + 7][nl] = a1.w;
        sW[kq + 0][ml] = w0.x; sW[kq + 1][ml] = w0.y; sW[kq + 2][ml] = w0.z; sW[kq + 3][ml] = w0.w;
        __syncthreads();
#pragma unroll
        for (int k = 0; k < 16; k++) {
            float4 av  = *(const float4*)&sA[k][tn * 4];
            float4 wv0 = *(const float4*)&sW[k][tm * 8];
            float4 wv1 = *(const float4*)&sW[k][tm * 8 + 4];
            float a[4] = {av.x, av.y, av.z, av.w};
            float w[8] = {wv0.x, wv0.y, wv0.z, wv0.w, wv1.x, wv1.y, wv1.z, wv1.w};
#pragma unroll
            for (int mi = 0; mi < 8; mi++)
#pragma unroll
                for (int nj = 0; nj < 4; nj++) acc[mi][nj] += w[mi] * a[nj];
        }
        __syncthreads();
    }
#pragma unroll
    for (int nj = 0; nj < 4; nj++) {
        int n = nb + tn * 4 + nj;
        int win = n / 49, tok = n - win * 49;
        int bb  = win >> 6;
        int whh = (win >> 3) & 7;
        int www = win & 7;
        int ti = tok / 7, tj = tok - ti * 7;
        int hi = whh * 7 + ti + kShift; if (hi >= kH) hi -= kH;
        int wi = www * 7 + tj + kShift; if (wi >= kW) wi -= kW;
#pragma unroll
        for (int mi = 0; mi < 8; mi++) {
            int m = mb + tm * 8 + mi;   // output channel
            float val = acc[mi][nj] + bias[m];
            size_t idx = ((size_t)(bb * kC + m) * kH + hi) * kW + wi;
            g_x1[idx] = xin[idx] + val;
        }
    }
}

// ---------------- 3x3 conv via tf32 tensor-core MMA --------------------------
// Block: 128 threads (4 warps), tile = 8 rows x 16 cols pixels (M=128), N=64 oc.
// Warp grid 2(M)x2(N): warp tile 64 px x 32 oc = 4 m16-frags x 4 n8-frags.
// K walked as (8-channel chunk) x (9 taps); each tap = one k8 MMA step.
template<int PH>
__global__ __launch_bounds__(128) void conv3x3_mma_kernel(const float* __restrict__ bias,
                                                          float* __restrict__ outp) {
    constexpr int IC = (PH == 0) ? kC : kHid;
    constexpr int OC = (PH == 0) ? kHid : kC;
    const float* in = (PH == 0) ? g_h0 : g_h1;
    const float* wt = (PH == 0) ? g_wt1 : g_wt2;
    float* out = (PH == 0) ? g_h1 : outp;

    const int b = blockIdx.z;
    const int ob = blockIdx.y * 64;
    const int rt = blockIdx.x >> 2, ct = blockIdx.x & 3;
    const int r0 = rt * 8, c0col = ct * 16;

    const int tid = threadIdx.x;
    const int warp = tid >> 5, lane = tid & 31;
    const int g = lane >> 2, t = lane & 3;     // groupID, threadID-in-group
    const int wm = warp >> 1, wn = warp & 1;   // warp M/N coords

    __shared__ unsigned sx[8][10][20];   // [chan][row+halo][col+halo], padded to 20
    __shared__ unsigned sw[72][64];      // [(c*9+tap)][oc]

    float acc[4][4][4];                  // [mfrag][nfrag][4]
#pragma unroll
    for (int i = 0; i < 4; i++)
#pragma unroll
        for (int j = 0; j < 4; j++)
#pragma unroll
            for (int k = 0; k < 4; k++) acc[i][j][k] = 0.f;

    for (int c0 = 0; c0 < IC; c0 += 8) {
        __syncthreads();
        // stage input patch: 8 ch x 10 x 18 (halo, zero pad), tf32-rounded
        for (int i = tid; i < 8 * 180; i += 128) {
            int c = i / 180, rem = i - c * 180;
            int y = rem / 18, x = rem - y * 18;
            int gy = r0 + y - 1, gx = c0col + x - 1;
            float v = 0.f;
            if (gy >= 0 && gy < kH && gx >= 0 && gx < kW)
                v = in[((size_t)(b * IC + c0 + c) * kH + gy) * kW + gx];
            sx[c][y][x] = f2tf32(v);
        }
        // stage weights: 72 k-rows x 64 oc, tf32-rounded (coalesced over oc)
        const float* wp = wt + (size_t)c0 * 9 * OC + ob;
        for (int i = tid; i < 72 * 64; i += 128) {
            int row = i >> 6, n = i & 63;
            sw[row][n] = f2tf32(wp[(size_t)row * OC + n]);
        }
        __syncthreads();
#pragma unroll
        for (int dy = 0; dy < 3; dy++) {
#pragma unroll
            for (int dx = 0; dx < 3; dx++) {
                unsigned afr[4][4];
#pragma unroll
                for (int mf = 0; mf < 4; mf++) {
                    const int ys = wm * 4 + mf + dy;
                    afr[mf][0] = sx[t    ][ys][g + dx];
                    afr[mf][1] = sx[t    ][ys][g + 8 + dx];
                    afr[mf][2] = sx[t + 4][ys][g + dx];
                    afr[mf][3] = sx[t + 4][ys][g + 8 + dx];
                }
                const int krow0 = t * 9 + dy * 3 + dx;
                const int krow1 = (t + 4) * 9 + dy * 3 + dx;
                unsigned bfr[4][2];
#pragma unroll
                for (int nf = 0; nf < 4; nf++) {
                    bfr[nf][0] = sw[krow0][wn * 32 + nf * 8 + g];
                    bfr[nf][1] = sw[krow1][wn * 32 + nf * 8 + g];
                }
#pragma unroll
                for (int mf = 0; mf < 4; mf++)
#pragma unroll
                    for (int nf = 0; nf < 4; nf++)
                        mma_tf32(acc[mf][nf], afr[mf], bfr[nf]);
            }
        }
    }

    // epilogue: D frag (16x8): d0 (px=g, n=2t), d1 (px=g, n=2t+1),
    //                          d2 (px=g+8, n=2t), d3 (px=g+8, n=2t+1)
#pragma unroll
    for (int mf = 0; mf < 4; mf++) {
        const int gy = r0 + wm * 4 + mf;
        const int gx0 = c0col + g;        // always < 56
        const int gx1 = c0col + g + 8;    // may exceed 55
#pragma unroll
        for (int nf = 0; nf < 4; nf++) {
            const int o = ob + wn * 32 + nf * 8 + 2 * t;
            const float bv0 = bias[o], bv1 = bias[o + 1];
            float v00 = acc[mf][nf][0] + bv0;
            float v01 = acc[mf][nf][1] + bv1;
            float v10 = acc[mf][nf][2] + bv0;
            float v11 = acc[mf][nf][3] + bv1;
            const size_t base0 = ((size_t)(b * OC + o) * kH + gy) * kW;
            const size_t base1 = ((size_t)(b * OC + o + 1) * kH + gy) * kW;
            if (PH == 0) {
                out[base0 + gx0] = 0.5f * v00 * (1.f + erff(v00 * 0.70710678118654752f));
                out[base1 + gx0] = 0.5f * v01 * (1.f + erff(v01 * 0.70710678118654752f));
                if (gx1 < kW) {
                    out[base0 + gx1] = 0.5f * v10 * (1.f + erff(v10 * 0.70710678118654752f));
                    out[base1 + gx1] = 0.5f * v11 * (1.f + erff(v11 * 0.70710678118654752f));
                }
            } else {
                out[base0 + gx0] = v00 + g_x1[base0 + gx0];
                out[base1 + gx0] = v01 + g_x1[base1 + gx0];
                if (gx1 < kW) {
                    out[base0 + gx1] = v10 + g_x1[base0 + gx1];
                    out[base1 + gx1] = v11 + g_x1[base1 + gx1];
                }
            }
        }
    }
}

// ---------------- launch -----------------------------------------------------
extern "C" void kernel_launch(void* const* d_in, const int* in_sizes, int n_in,
                              void* d_out, int out_size) {
    (void)in_sizes; (void)n_in; (void)out_size;
    const float* x       = (const float*)d_in[0];
    const float* ln1_g   = (const float*)d_in[1];
    const float* ln1_b   = (const float*)d_in[2];
    const float* qkv_w   = (const float*)d_in[3];
    const float* qkv_b   = (const float*)d_in[4];
    const float* proj_w  = (const float*)d_in[5];
    const float* proj_b  = (const float*)d_in[6];
    const float* ln2_g   = (const float*)d_in[7];
    const float* ln2_b   = (const float*)d_in[8];
    const float* conv1_w = (const float*)d_in[9];
    const float* conv1_b = (const float*)d_in[10];
    const float* conv2_w = (const float*)d_in[11];
    const float* conv2_b = (const float*)d_in[12];
    float* out = (float*)d_out;

    wtrans_kernel<0><<<(kHid * kC * 9 + 255) / 256, 256>>>(conv1_w);
    wtrans_kernel<1><<<(kC * kHid * 9 + 255) / 256, 256>>>(conv2_w);

    ln_kernel<0><<<kNT / 256, 256>>>(x, ln1_g, ln1_b);
    gemm_qkv_kernel<<<dim3(kNT / 128, (3 * kC) / 64), 256>>>(qkv_w, qkv_b);
    attn_kernel<<<kNWin * kHeads, 64>>>();
    gemm_proj_kernel<<<dim3(kNT / 128, kC / 64), 256>>>(proj_w, proj_b, x);
    ln_kernel<1><<<kNT / 256, 256>>>(nullptr, ln2_g, ln2_b);
    conv3x3_mma_kernel<0><<<dim3(28, kHid / 64, kB), 128>>>(conv1_b, nullptr);
    conv3x3_mma_kernel<1><<<dim3(28, kC / 64, kB), 128>>>(conv2_b, out);
}

// round 3
// speedup vs baseline: 1.8211x; 1.0209x over previous
#include <cuda_runtime.h>
#include <math.h>

namespace {
constexpr int kB = 32, kC = 192, kH = 56, kW = 56;
constexpr int kHeads = 6, kD = 32, kWS = 7, kShift = 3, kHid = 768;
constexpr int kNWin = kB * 8 * 8;   // 2048 windows
constexpr int kTok = kWS * kWS;     // 49
constexpr int kNT = kNWin * kTok;   // 100352 tokens
constexpr int kHWp = kH * kW;       // 3136
}

// ---------------- scratch (static __device__, allocation-free) ----------------
__device__ float g_wt1[kC * 9 * kHid];          // conv1 weights transposed [(c*9+t), o]
__device__ float g_wt2[kHid * 9 * kC];          // conv2 weights transposed
__device__ float g_xw[(size_t)kNT * kC];        // LN1 output, window layout [win][tok][c]
__device__ float g_q [(size_t)kNT * kC];        // q [win][head][tok][d]
__device__ float g_kk[(size_t)kNT * kC];        // k
__device__ float g_vv[(size_t)kNT * kC];        // v
__device__ float g_ao[(size_t)kNT * kC];        // attention out [win][tok][c]
__device__ float g_x1[(size_t)kNT * kC];        // x + attn branch (NCHW)
__device__ float g_h0[(size_t)kNT * kC];        // LN2 out (NCHW)
__device__ float g_h1[(size_t)kNT * kHid];      // conv1+gelu out (NCHW, 768ch)

// ---------------- helpers ----------------------------------------------------
__device__ __forceinline__ unsigned f2tf32(float x) {
    unsigned r; asm("cvt.rna.tf32.f32 %0, %1;" : "=r"(r) : "f"(x)); return r;
}
__device__ __forceinline__ void mma_tf32(float* d, const unsigned* a, const unsigned* b) {
    asm volatile(
        "mma.sync.aligned.m16n8k8.row.col.f32.tf32.tf32.f32 "
        "{%0,%1,%2,%3}, {%4,%5,%6,%7}, {%8,%9}, {%0,%1,%2,%3};\n"
        : "+f"(d[0]), "+f"(d[1]), "+f"(d[2]), "+f"(d[3])
        : "r"(a[0]), "r"(a[1]), "r"(a[2]), "r"(a[3]), "r"(b[0]), "r"(b[1]));
}

// ---------------- weight transpose:  w[o][c][t] -> wt[(c*9+t)*OC + o] --------
template<int PH>
__global__ void wtrans_kernel(const float* __restrict__ w) {
    constexpr int OC = (PH == 0) ? kHid : kC;
    constexpr int IC = (PH == 0) ? kC : kHid;
    float* wt = (PH == 0) ? g_wt1 : g_wt2;
    int i = blockIdx.x * 256 + threadIdx.x;
    if (i < OC * IC * 9) {
        int o = i / (IC * 9);
        int ct = i - o * (IC * 9);
        wt[(size_t)ct * OC + o] = w[i];
    }
}

// ---------------- LayerNorm over C; MODE 0: x -> g_xw (roll + window) --------
// ----------------                    MODE 1: g_x1 -> g_h0 (plain NCHW) -------
template<int MODE>
__global__ void ln_kernel(const float* __restrict__ xin,
                          const float* __restrict__ gam,
                          const float* __restrict__ bet) {
    int p = blockIdx.x * 256 + threadIdx.x;
    if (p >= kNT) return;
    const float* src = (MODE == 0) ? xin : g_x1;
    int b = p / kHWp;
    int rem = p - b * kHWp;
    int hp = rem / kW, wp = rem - (rem / kW) * kW;
    int h = hp, w = wp;
    if (MODE == 0) {  // rolled frame pixel hp reads source (hp+shift) mod H
        h = hp + kShift; if (h >= kH) h -= kH;
        w = wp + kShift; if (w >= kW) w -= kW;
    }
    const float* xp = src + ((size_t)b * kC) * kHWp + h * kW + w;
    float s = 0.f, s2 = 0.f;
#pragma unroll 4
    for (int c = 0; c < kC; c++) { float v = xp[(size_t)c * kHWp]; s += v; s2 += v * v; }
    float m = s * (1.f / kC);
    float var = s2 * (1.f / kC) - m * m;
    float rs = rsqrtf(var + 1e-5f);
    if (MODE == 0) {
        int win = b * 64 + (hp / 7) * 8 + (wp / 7);
        int tok = (hp % 7) * 7 + (wp % 7);
        float* op = g_xw + ((size_t)win * kTok + tok) * kC;
#pragma unroll 4
        for (int c = 0; c < kC; c++)
            op[c] = (xp[(size_t)c * kHWp] - m) * rs * gam[c] + bet[c];
    } else {
        float* op = g_h0 + ((size_t)b * kC) * kHWp + h * kW + w;
#pragma unroll 4
        for (int c = 0; c < kC; c++)
            op[(size_t)c * kHWp] = (xp[(size_t)c * kHWp] - m) * rs * gam[c] + bet[c];
    }
}

// ---------------- GEMM via tf32 MMA: out[tok][m] = A[tok][c] . W[m][c] -------
// Block 256 thr, tile 256 tok x 64 out, k-chunk 16. Warp = 64 tok x 32 out.
// EPI 0: A = g_xw, scatter to q/k/v.   EPI 1: A = g_ao, inverse-roll + resid.
template<int EPI>
__global__ __launch_bounds__(256) void gemm_mma_kernel(const float* __restrict__ Wm,
                                                       const float* __restrict__ bias,
                                                       const float* __restrict__ xin) {
    __shared__ unsigned sA[16][264];
    __shared__ unsigned sW[16][72];
    const float* A = (EPI == 0) ? g_xw : g_ao;
    const int tid = threadIdx.x;
    const int warp = tid >> 5, lane = tid & 31;
    const int g = lane >> 2, t = lane & 3;
    const int wm = warp >> 1, wn = warp & 1;
    const int tokbase = blockIdx.x * 256;
    const int ob = blockIdx.y * 64;

    float acc[4][4][4];
#pragma unroll
    for (int i = 0; i < 4; i++)
#pragma unroll
        for (int j = 0; j < 4; j++)
#pragma unroll
            for (int k = 0; k < 4; k++) acc[i][j][k] = 0.f;

    for (int k0 = 0; k0 < kC; k0 += 16) {
        __syncthreads();
        // stage A: 256 tok x 16 c, transposed to [k][m]
#pragma unroll
        for (int i = tid; i < 1024; i += 256) {
            int tl = i >> 2, kq = (i & 3) << 2;
            float4 v = *(const float4*)(A + (size_t)(tokbase + tl) * kC + k0 + kq);
            sA[kq + 0][tl] = f2tf32(v.x);
            sA[kq + 1][tl] = f2tf32(v.y);
            sA[kq + 2][tl] = f2tf32(v.z);
            sA[kq + 3][tl] = f2tf32(v.w);
        }
        // stage W: 64 out x 16 c, transposed to [k][n]
        {
            int n = tid >> 2, kq = (tid & 3) << 2;
            float4 v = *(const float4*)(Wm + (size_t)(ob + n) * kC + k0 + kq);
            sW[kq + 0][n] = f2tf32(v.x);
            sW[kq + 1][n] = f2tf32(v.y);
            sW[kq + 2][n] = f2tf32(v.z);
            sW[kq + 3][n] = f2tf32(v.w);
        }
        __syncthreads();
#pragma unroll
        for (int s = 0; s < 2; s++) {
            unsigned afr[4][4];
#pragma unroll
            for (int mf = 0; mf < 4; mf++) {
                const int mbase = wm * 64 + mf * 16;
                afr[mf][0] = sA[s * 8 + t    ][mbase + g];
                afr[mf][1] = sA[s * 8 + t    ][mbase + g + 8];
                afr[mf][2] = sA[s * 8 + t + 4][mbase + g];
                afr[mf][3] = sA[s * 8 + t + 4][mbase + g + 8];
            }
            unsigned bfr[4][2];
#pragma unroll
            for (int nf = 0; nf < 4; nf++) {
                bfr[nf][0] = sW[s * 8 + t    ][wn * 32 + nf * 8 + g];
                bfr[nf][1] = sW[s * 8 + t + 4][wn * 32 + nf * 8 + g];
            }
#pragma unroll
            for (int mf = 0; mf < 4; mf++)
#pragma unroll
                for (int nf = 0; nf < 4; nf++)
                    mma_tf32(acc[mf][nf], afr[mf], bfr[nf]);
        }
    }

    // epilogue: d0 (tok=base+g, o=2t), d1 (o=2t+1), d2 (tok+8, 2t), d3 (tok+8, 2t+1)
#pragma unroll
    for (int mf = 0; mf < 4; mf++) {
        const int tk0 = tokbase + wm * 64 + mf * 16 + g;
#pragma unroll
        for (int nf = 0; nf < 4; nf++) {
            const int o0 = ob + wn * 32 + nf * 8 + 2 * t;
            const float bv0 = bias[o0], bv1 = bias[o0 + 1];
            float vals[4] = {acc[mf][nf][0] + bv0, acc[mf][nf][1] + bv1,
                             acc[mf][nf][2] + bv0, acc[mf][nf][3] + bv1};
#pragma unroll
            for (int q = 0; q < 4; q++) {
                const int n_tok = tk0 + (q >> 1) * 8;
                const int mo = o0 + (q & 1);
                const int win = n_tok / 49, tok = n_tok - win * 49;
                if (EPI == 0) {
                    int sec = mo / kC;
                    int c = mo - sec * kC;
                    float* dst = (sec == 0) ? g_q : (sec == 1) ? g_kk : g_vv;
                    dst[((size_t)(win * kHeads + (c >> 5)) * kTok + tok) * kD + (c & 31)] = vals[q];
                } else {
                    int bb  = win >> 6;
                    int whh = (win >> 3) & 7;
                    int www = win & 7;
                    int ti = tok / 7, tj = tok - ti * 7;
                    int hi = whh * 7 + ti + kShift; if (hi >= kH) hi -= kH;
                    int wi = www * 7 + tj + kShift; if (wi >= kW) wi -= kW;
                    size_t idx = ((size_t)(bb * kC + mo) * kH + hi) * kW + wi;
                    g_x1[idx] = xin[idx] + vals[q];
                }
            }
        }
    }
}

// ---------------- attention: one block per (window, head), scores in regs ----
__global__ __launch_bounds__(64) void attn_kernel() {
    const int wh = blockIdx.x;  // win*6 + head
    __shared__ float sq[kTok * 33], sk[kTok * kD], sv[kTok * kD];
    const size_t base = (size_t)wh * kTok * kD;
    for (int i = threadIdx.x; i < kTok * kD; i += 64) {
        int r = i >> 5, d = i & 31;
        sq[r * 33 + d] = g_q[base + i];
        sk[i] = g_kk[base + i];
        sv[i] = g_vv[base + i];
    }
    __syncthreads();
    const int r = threadIdx.x;
    if (r < kTok) {
        float qr[kD];
#pragma unroll
        for (int d = 0; d < kD; d++) qr[d] = sq[r * 33 + d];
        float p[kTok];
        float mx = -1e30f;
#pragma unroll
        for (int m = 0; m < kTok; m++) {
            float dot = 0.f;
#pragma unroll
            for (int d = 0; d < kD; d++) dot += qr[d] * sk[m * kD + d];
            dot *= 0.17677669529663689f;   // 32^-0.5
            p[m] = dot;
            mx = fmaxf(mx, dot);
        }
        float sum = 0.f;
#pragma unroll
        for (int m = 0; m < kTok; m++) { p[m] = __expf(p[m] - mx); sum += p[m]; }
        const float inv = 1.f / sum;
        const int win = wh / kHeads, head = wh - win * kHeads;
        float* op = g_ao + ((size_t)win * kTok + r) * kC + head * kD;
#pragma unroll 4
        for (int d = 0; d < kD; d++) {
            float a = 0.f;
#pragma unroll
            for (int m = 0; m < kTok; m++) a += p[m] * sv[m * kD + d];
            op[d] = a * inv;
        }
    }
}

// ---------------- 3x3 conv via tf32 MMA, v2 ----------------------------------
// Block 256 thr (8 warps), tile 8 rows x 32 cols (M=256 px), N=64 oc.
// Warp = 2 rows x 32 cols x 32 oc: mf = (row r 0..1, colgroup cg 0..1), nf 0..3.
// smem padded conflict-free: sx stride 36, sw stride 72.
template<int PH>
__global__ __launch_bounds__(256) void conv3x3_mma_kernel(const float* __restrict__ bias,
                                                          float* __restrict__ outp) {
    constexpr int IC = (PH == 0) ? kC : kHid;
    constexpr int OC = (PH == 0) ? kHid : kC;
    const float* in = (PH == 0) ? g_h0 : g_h1;
    const float* wt = (PH == 0) ? g_wt1 : g_wt2;
    float* out = (PH == 0) ? g_h1 : outp;

    const int b = blockIdx.z;
    const int ob = blockIdx.y * 64;
    const int rt = blockIdx.x >> 1, ct = blockIdx.x & 1;
    const int r0 = rt * 8, c0col = ct * 32;

    const int tid = threadIdx.x;
    const int warp = tid >> 5, lane = tid & 31;
    const int g = lane >> 2, t = lane & 3;
    const int wm = warp >> 1, wn = warp & 1;   // wm 0..3 (2 rows each), wn 0..1

    __shared__ unsigned sx[8][10][36];   // [chan][row+halo][col padded]
    __shared__ unsigned sw[72][72];      // [(c*9+tap)][oc padded]  stride 72 => conflict-free

    float acc[4][4][4];
#pragma unroll
    for (int i = 0; i < 4; i++)
#pragma unroll
        for (int j = 0; j < 4; j++)
#pragma unroll
            for (int k = 0; k < 4; k++) acc[i][j][k] = 0.f;

    for (int c0 = 0; c0 < IC; c0 += 8) {
        __syncthreads();
        // stage input patch: 8 ch x 10 x 34 (halo, zero pad)
        for (int i = tid; i < 8 * 340; i += 256) {
            int c = i / 340, rem = i - c * 340;
            int y = rem / 34, x = rem - y * 34;
            int gy = r0 + y - 1, gx = c0col + x - 1;
            float v = 0.f;
            if (gy >= 0 && gy < kH && gx >= 0 && gx < kW)
                v = in[((size_t)(b * IC + c0 + c) * kH + gy) * kW + gx];
            sx[c][y][x] = f2tf32(v);
        }
        // stage weights: 72 k-rows x 64 oc
        const float* wp = wt + (size_t)c0 * 9 * OC + ob;
        for (int i = tid; i < 72 * 64; i += 256) {
            int row = i >> 6, n = i & 63;
            sw[row][n] = f2tf32(wp[(size_t)row * OC + n]);
        }
        __syncthreads();
#pragma unroll
        for (int dy = 0; dy < 3; dy++) {
#pragma unroll
            for (int dx = 0; dx < 3; dx++) {
                unsigned afr[4][4];
#pragma unroll
                for (int mf = 0; mf < 4; mf++) {
                    const int ys = wm * 2 + (mf >> 1) + dy;
                    const int xb = (mf & 1) * 16 + g + dx;
                    afr[mf][0] = sx[t    ][ys][xb];
                    afr[mf][1] = sx[t    ][ys][xb + 8];
                    afr[mf][2] = sx[t + 4][ys][xb];
                    afr[mf][3] = sx[t + 4][ys][xb + 8];
                }
                const int krow0 = t * 9 + dy * 3 + dx;
                const int krow1 = (t + 4) * 9 + dy * 3 + dx;
                unsigned bfr[4][2];
#pragma unroll
                for (int nf = 0; nf < 4; nf++) {
                    bfr[nf][0] = sw[krow0][wn * 32 + nf * 8 + g];
                    bfr[nf][1] = sw[krow1][wn * 32 + nf * 8 + g];
                }
#pragma unroll
                for (int mf = 0; mf < 4; mf++)
#pragma unroll
                    for (int nf = 0; nf < 4; nf++)
                        mma_tf32(acc[mf][nf], afr[mf], bfr[nf]);
            }
        }
    }

    // epilogue: d0 (px=g, o=2t), d1 (px=g, o=2t+1), d2 (px=g+8, 2t), d3 (px=g+8, 2t+1)
#pragma unroll
    for (int mf = 0; mf < 4; mf++) {
        const int gy = r0 + wm * 2 + (mf >> 1);
        const int gxA = c0col + (mf & 1) * 16 + g;
        const int gxB = gxA + 8;
        const bool okA = gxA < kW, okB = gxB < kW;
#pragma unroll
        for (int nf = 0; nf < 4; nf++) {
            const int o = ob + wn * 32 + nf * 8 + 2 * t;
            const float bv0 = bias[o], bv1 = bias[o + 1];
            float v00 = acc[mf][nf][0] + bv0;
            float v01 = acc[mf][nf][1] + bv1;
            float v10 = acc[mf][nf][2] + bv0;
            float v11 = acc[mf][nf][3] + bv1;
            const size_t base0 = ((size_t)(b * OC + o) * kH + gy) * kW;
            const size_t base1 = ((size_t)(b * OC + o + 1) * kH + gy) * kW;
            if (PH == 0) {
                if (okA) {
                    out[base0 + gxA] = 0.5f * v00 * (1.f + erff(v00 * 0.70710678118654752f));
                    out[base1 + gxA] = 0.5f * v01 * (1.f + erff(v01 * 0.70710678118654752f));
                }
                if (okB) {
                    out[base0 + gxB] = 0.5f * v10 * (1.f + erff(v10 * 0.70710678118654752f));
                    out[base1 + gxB] = 0.5f * v11 * (1.f + erff(v11 * 0.70710678118654752f));
                }
            } else {
                if (okA) {
                    out[base0 + gxA] = v00 + g_x1[base0 + gxA];
                    out[base1 + gxA] = v01 + g_x1[base1 + gxA];
                }
                if (okB) {
                    out[base0 + gxB] = v10 + g_x1[base0 + gxB];
                    out[base1 + gxB] = v11 + g_x1[base1 + gxB];
                }
            }
        }
    }
}

// ---------------- launch -----------------------------------------------------
extern "C" void kernel_launch(void* const* d_in, const int* in_sizes, int n_in,
                              void* d_out, int out_size) {
    (void)in_sizes; (void)n_in; (void)out_size;
    const float* x       = (const float*)d_in[0];
    const float* ln1_g   = (const float*)d_in[1];
    const float* ln1_b   = (const float*)d_in[2];
    const float* qkv_w   = (const float*)d_in[3];
    const float* qkv_b   = (const float*)d_in[4];
    const float* proj_w  = (const float*)d_in[5];
    const float* proj_b  = (const float*)d_in[6];
    const float* ln2_g   = (const float*)d_in[7];
    const float* ln2_b   = (const float*)d_in[8];
    const float* conv1_w = (const float*)d_in[9];
    const float* conv1_b = (const float*)d_in[10];
    const float* conv2_w = (const float*)d_in[11];
    const float* conv2_b = (const float*)d_in[12];
    float* out = (float*)d_out;

    wtrans_kernel<0><<<(kHid * kC * 9 + 255) / 256, 256>>>(conv1_w);
    wtrans_kernel<1><<<(kC * kHid * 9 + 255) / 256, 256>>>(conv2_w);

    ln_kernel<0><<<kNT / 256, 256>>>(x, ln1_g, ln1_b);
    gemm_mma_kernel<0><<<dim3(kNT / 256, (3 * kC) / 64), 256>>>(qkv_w, qkv_b, nullptr);
    attn_kernel<<<kNWin * kHeads, 64>>>();
    gemm_mma_kernel<1><<<dim3(kNT / 256, kC / 64), 256>>>(proj_w, proj_b, x);
    ln_kernel<1><<<kNT / 256, 256>>>(nullptr, ln2_g, ln2_b);
    conv3x3_mma_kernel<0><<<dim3(14, kHid / 64, kB), 256>>>(conv1_b, nullptr);
    conv3x3_mma_kernel<1><<<dim3(14, kC / 64, kB), 256>>>(conv2_b, out);
}

// round 4
// speedup vs baseline: 3.7837x; 2.0777x over previous
#include <cuda_runtime.h>
#include <math.h>

namespace {
constexpr int kB = 32, kC = 192, kH = 56, kW = 56;
constexpr int kHeads = 6, kD = 32, kWS = 7, kShift = 3, kHid = 768;
constexpr int kNWin = kB * 8 * 8;   // 2048 windows
constexpr int kTok = kWS * kWS;     // 49
constexpr int kNT = kNWin * kTok;   // 100352 tokens
constexpr int kHWp = kH * kW;       // 3136
}

// ---------------- scratch (static __device__, allocation-free) ----------------
__device__ float g_wt1[kC * 9 * kHid];          // conv1 weights transposed, tf32-rounded
__device__ float g_wt2[kHid * 9 * kC];
__device__ float g_xw[(size_t)kNT * kC];        // LN1 out, window layout [win][tok][c]
__device__ float g_q [(size_t)kNT * kC];
__device__ float g_kk[(size_t)kNT * kC];
__device__ float g_vv[(size_t)kNT * kC];
__device__ float g_ao[(size_t)kNT * kC];        // attention out [win][tok][c]
__device__ float g_x1[(size_t)kNT * kC];        // x + attn branch (NCHW)
__device__ float g_h0[(size_t)kNT * kC];        // LN2 out (NCHW), tf32-rounded
__device__ float g_h1[(size_t)kNT * kHid];      // conv1+gelu out (NCHW), tf32-rounded

// ---------------- helpers ----------------------------------------------------
__device__ __forceinline__ unsigned f2tf32(float x) {
    unsigned r; asm("cvt.rna.tf32.f32 %0, %1;" : "=r"(r) : "f"(x)); return r;
}
__device__ __forceinline__ void mma_tf32(float* d, const unsigned* a, const unsigned* b) {
    asm volatile(
        "mma.sync.aligned.m16n8k8.row.col.f32.tf32.tf32.f32 "
        "{%0,%1,%2,%3}, {%4,%5,%6,%7}, {%8,%9}, {%0,%1,%2,%3};\n"
        : "+f"(d[0]), "+f"(d[1]), "+f"(d[2]), "+f"(d[3])
        : "r"(a[0]), "r"(a[1]), "r"(a[2]), "r"(a[3]), "r"(b[0]), "r"(b[1]));
}
__device__ __forceinline__ void cp4(unsigned dst, const void* src, int sz) {
    asm volatile("cp.async.ca.shared.global [%0], [%1], 4, %2;" :: "r"(dst), "l"(src), "r"(sz));
}
__device__ __forceinline__ void cp16(unsigned dst, const void* src) {
    asm volatile("cp.async.cg.shared.global [%0], [%1], 16;" :: "r"(dst), "l"(src));
}

// ---------------- weight transpose:  w[o][c][t] -> wt[(c*9+t)*OC + o] --------
template<int PH>
__global__ void wtrans_kernel(const float* __restrict__ w) {
    constexpr int OC = (PH == 0) ? kHid : kC;
    constexpr int IC = (PH == 0) ? kC : kHid;
    float* wt = (PH == 0) ? g_wt1 : g_wt2;
    int i = blockIdx.x * 256 + threadIdx.x;
    if (i < OC * IC * 9) {
        int o = i / (IC * 9);
        int ct = i - o * (IC * 9);
        wt[(size_t)ct * OC + o] = __uint_as_float(f2tf32(w[i]));
    }
}

// ---------------- LayerNorm over C; MODE 0: x -> g_xw (roll + window) --------
// ----------------                    MODE 1: g_x1 -> g_h0 (tf32-rounded) -----
template<int MODE>
__global__ void ln_kernel(const float* __restrict__ xin,
                          const float* __restrict__ gam,
                          const float* __restrict__ bet) {
    int p = blockIdx.x * 256 + threadIdx.x;
    if (p >= kNT) return;
    const float* src = (MODE == 0) ? xin : g_x1;
    int b = p / kHWp;
    int rem = p - b * kHWp;
    int hp = rem / kW, wp = rem - (rem / kW) * kW;
    int h = hp, w = wp;
    if (MODE == 0) {
        h = hp + kShift; if (h >= kH) h -= kH;
        w = wp + kShift; if (w >= kW) w -= kW;
    }
    const float* xp = src + ((size_t)b * kC) * kHWp + h * kW + w;
    float s = 0.f, s2 = 0.f;
#pragma unroll 4
    for (int c = 0; c < kC; c++) { float v = xp[(size_t)c * kHWp]; s += v; s2 += v * v; }
    float m = s * (1.f / kC);
    float var = s2 * (1.f / kC) - m * m;
    float rs = rsqrtf(var + 1e-5f);
    if (MODE == 0) {
        int win = b * 64 + (hp / 7) * 8 + (wp / 7);
        int tok = (hp % 7) * 7 + (wp % 7);
        float* op = g_xw + ((size_t)win * kTok + tok) * kC;
#pragma unroll 4
        for (int c = 0; c < kC; c++)
            op[c] = (xp[(size_t)c * kHWp] - m) * rs * gam[c] + bet[c];
    } else {
        float* op = g_h0 + ((size_t)b * kC) * kHWp + h * kW + w;
#pragma unroll 4
        for (int c = 0; c < kC; c++) {
            float v = (xp[(size_t)c * kHWp] - m) * rs * gam[c] + bet[c];
            op[(size_t)c * kHWp] = __uint_as_float(f2tf32(v));
        }
    }
}

// ---------------- GEMM via tf32 MMA: 128 thr, warp = 64 tok x 64 out ---------
// Block tile 256 tok x 64 out. EPI 0: A=g_xw -> q/k/v. EPI 1: A=g_ao -> resid.
template<int EPI>
__global__ __launch_bounds__(128, 2) void gemm_mma_kernel(const float* __restrict__ Wm,
                                                          const float* __restrict__ bias,
                                                          const float* __restrict__ xin) {
    __shared__ unsigned sA[16][264];
    __shared__ unsigned sW[16][72];
    const float* A = (EPI == 0) ? g_xw : g_ao;
    const int tid = threadIdx.x;
    const int warp = tid >> 5, lane = tid & 31;
    const int g = lane >> 2, t = lane & 3;
    const int wm = warp;                 // 0..3, 64 tokens each
    const int tokbase = blockIdx.x * 256;
    const int ob = blockIdx.y * 64;

    float acc[4][8][4];
#pragma unroll
    for (int i = 0; i < 4; i++)
#pragma unroll
        for (int j = 0; j < 8; j++)
#pragma unroll
            for (int k = 0; k < 4; k++) acc[i][j][k] = 0.f;

    for (int k0 = 0; k0 < kC; k0 += 16) {
        __syncthreads();
#pragma unroll
        for (int i = tid; i < 1024; i += 128) {
            int tl = i >> 2, kq = (i & 3) << 2;
            float4 v = *(const float4*)(A + (size_t)(tokbase + tl) * kC + k0 + kq);
            sA[kq + 0][tl] = f2tf32(v.x);
            sA[kq + 1][tl] = f2tf32(v.y);
            sA[kq + 2][tl] = f2tf32(v.z);
            sA[kq + 3][tl] = f2tf32(v.w);
        }
#pragma unroll
        for (int i = tid; i < 256; i += 128) {
            int n = i >> 2, kq = (i & 3) << 2;
            float4 v = *(const float4*)(Wm + (size_t)(ob + n) * kC + k0 + kq);
            sW[kq + 0][n] = f2tf32(v.x);
            sW[kq + 1][n] = f2tf32(v.y);
            sW[kq + 2][n] = f2tf32(v.z);
            sW[kq + 3][n] = f2tf32(v.w);
        }
        __syncthreads();
#pragma unroll
        for (int s = 0; s < 2; s++) {
            unsigned afr[4][4];
#pragma unroll
            for (int mf = 0; mf < 4; mf++) {
                const int mbase = wm * 64 + mf * 16;
                afr[mf][0] = sA[s * 8 + t    ][mbase + g];
                afr[mf][1] = sA[s * 8 + t    ][mbase + g + 8];
                afr[mf][2] = sA[s * 8 + t + 4][mbase + g];
                afr[mf][3] = sA[s * 8 + t + 4][mbase + g + 8];
            }
            unsigned bfr[8][2];
#pragma unroll
            for (int nf = 0; nf < 8; nf++) {
                bfr[nf][0] = sW[s * 8 + t    ][nf * 8 + g];
                bfr[nf][1] = sW[s * 8 + t + 4][nf * 8 + g];
            }
#pragma unroll
            for (int mf = 0; mf < 4; mf++)
#pragma unroll
                for (int nf = 0; nf < 8; nf++)
                    mma_tf32(acc[mf][nf], afr[mf], bfr[nf]);
        }
    }

#pragma unroll
    for (int mf = 0; mf < 4; mf++) {
        const int tk0 = tokbase + wm * 64 + mf * 16 + g;
#pragma unroll
        for (int nf = 0; nf < 8; nf++) {
            const int o0 = ob + nf * 8 + 2 * t;
            const float bv0 = bias[o0], bv1 = bias[o0 + 1];
            float vals[4] = {acc[mf][nf][0] + bv0, acc[mf][nf][1] + bv1,
                             acc[mf][nf][2] + bv0, acc[mf][nf][3] + bv1};
#pragma unroll
            for (int q = 0; q < 4; q++) {
                const int n_tok = tk0 + (q >> 1) * 8;
                const int mo = o0 + (q & 1);
                const int win = n_tok / 49, tok = n_tok - win * 49;
                if (EPI == 0) {
                    int sec = mo / kC;
                    int c = mo - sec * kC;
                    float* dst = (sec == 0) ? g_q : (sec == 1) ? g_kk : g_vv;
                    dst[((size_t)(win * kHeads + (c >> 5)) * kTok + tok) * kD + (c & 31)] = vals[q];
                } else {
                    int bb  = win >> 6;
                    int whh = (win >> 3) & 7;
                    int www = win & 7;
                    int ti = tok / 7, tj = tok - ti * 7;
                    int hi = whh * 7 + ti + kShift; if (hi >= kH) hi -= kH;
                    int wi = www * 7 + tj + kShift; if (wi >= kW) wi -= kW;
                    size_t idx = ((size_t)(bb * kC + mo) * kH + hi) * kW + wi;
                    g_x1[idx] = xin[idx] + vals[q];
                }
            }
        }
    }
}

// ---------------- attention: one block per (window, head), scores in regs ----
__global__ __launch_bounds__(64) void attn_kernel() {
    const int wh = blockIdx.x;
    __shared__ float sq[kTok * 33], sk[kTok * kD], sv[kTok * kD];
    const size_t base = (size_t)wh * kTok * kD;
    for (int i = threadIdx.x; i < kTok * kD; i += 64) {
        int r = i >> 5, d = i & 31;
        sq[r * 33 + d] = g_q[base + i];
        sk[i] = g_kk[base + i];
        sv[i] = g_vv[base + i];
    }
    __syncthreads();
    const int r = threadIdx.x;
    if (r < kTok) {
        float qr[kD];
#pragma unroll
        for (int d = 0; d < kD; d++) qr[d] = sq[r * 33 + d];
        float p[kTok];
        float mx = -1e30f;
#pragma unroll
        for (int m = 0; m < kTok; m++) {
            float dot = 0.f;
#pragma unroll
            for (int d = 0; d < kD; d++) dot += qr[d] * sk[m * kD + d];
            dot *= 0.17677669529663689f;
            p[m] = dot;
            mx = fmaxf(mx, dot);
        }
        float sum = 0.f;
#pragma unroll
        for (int m = 0; m < kTok; m++) { p[m] = __expf(p[m] - mx); sum += p[m]; }
        const float inv = 1.f / sum;
        const int win = wh / kHeads, head = wh - win * kHeads;
        float* op = g_ao + ((size_t)win * kTok + r) * kC + head * kD;
#pragma unroll 4
        for (int d = 0; d < kD; d++) {
            float a = 0.f;
#pragma unroll
            for (int m = 0; m < kTok; m++) a += p[m] * sv[m * kD + d];
            op[d] = a * inv;
        }
    }
}

// ---------------- 3x3 conv via tf32 MMA v3 -----------------------------------
// 128 thr / 4 warps, block tile 8 rows x 32 cols (256 px) x 64 oc.
// Warp = 2 rows x 32 cols x 64 oc. cp.async double-buffered staging.
// smem: sx[2][8][10][36], sw[2][72][72] (both conflict-free: stride % 32 == 8|matched).
template<int PH>
__global__ __launch_bounds__(128, 2) void conv3x3_mma_kernel(const float* __restrict__ bias,
                                                             float* __restrict__ outp) {
    constexpr int IC = (PH == 0) ? kC : kHid;
    constexpr int OC = (PH == 0) ? kHid : kC;
    constexpr int NCH = IC / 8;
    const float* in = (PH == 0) ? g_h0 : g_h1;
    const float* wt = (PH == 0) ? g_wt1 : g_wt2;
    float* out = (PH == 0) ? g_h1 : outp;

    const int b = blockIdx.z;
    const int ob = blockIdx.y * 64;
    const int rt = blockIdx.x >> 1, ct = blockIdx.x & 1;
    const int r0 = rt * 8, c0col = ct * 32;

    const int tid = threadIdx.x;
    const int warp = tid >> 5, lane = tid & 31;
    const int g = lane >> 2, t = lane & 3;
    const int wm = warp;                       // 0..3 -> rows [wm*2, wm*2+2)

    extern __shared__ unsigned smemd[];
    unsigned* sxb0 = smemd;                    // 2880 words each
    unsigned* sxb1 = smemd + 2880;
    unsigned* swb0 = smemd + 5760;             // 5184 words each
    unsigned* swb1 = smemd + 5760 + 5184;

    auto stage = [&](int ci, int bufi) {
        unsigned* sxb = bufi ? sxb1 : sxb0;
        unsigned* swb = bufi ? swb1 : swb0;
        const unsigned sx_base = (unsigned)__cvta_generic_to_shared(sxb);
        const float* inc = in + ((size_t)(b * IC + ci * 8) * kH) * kW;
        for (int i = tid; i < 8 * 340; i += 128) {
            int c = i / 340, rem = i - c * 340;
            int y = rem / 34, x = rem - y * 34;
            int gy = r0 + y - 1, gx = c0col + x - 1;
            bool ok = (gy >= 0 && gy < kH && gx >= 0 && gx < kW);
            const float* src = inc + (size_t)c * kHWp + (ok ? (gy * kW + gx) : 0);
            cp4(sx_base + (unsigned)(((c * 10 + y) * 36 + x) << 2), src, ok ? 4 : 0);
        }
        const float* wp = wt + (size_t)(ci * 8) * 9 * OC + ob;
        const unsigned sw_base = (unsigned)__cvta_generic_to_shared(swb);
        for (int i = tid; i < 72 * 16; i += 128) {
            int row = i >> 4, cq = (i & 15) << 2;
            cp16(sw_base + (unsigned)((row * 72 + cq) << 2), wp + (size_t)row * OC + cq);
        }
    };

    float acc[4][8][4];
#pragma unroll
    for (int i = 0; i < 4; i++)
#pragma unroll
        for (int j = 0; j < 8; j++)
#pragma unroll
            for (int k = 0; k < 4; k++) acc[i][j][k] = 0.f;

    stage(0, 0);
    asm volatile("cp.async.commit_group;");

    for (int ci = 0; ci < NCH; ci++) {
        if (ci + 1 < NCH) {
            stage(ci + 1, (ci + 1) & 1);
            asm volatile("cp.async.commit_group;");
            asm volatile("cp.async.wait_group 1;");
        } else {
            asm volatile("cp.async.wait_group 0;");
        }
        __syncthreads();
        const unsigned (*sx)[10][36] = (const unsigned(*)[10][36])((ci & 1) ? sxb1 : sxb0);
        const unsigned (*sw)[72]     = (const unsigned(*)[72])((ci & 1) ? swb1 : swb0);
#pragma unroll
        for (int dy = 0; dy < 3; dy++) {
#pragma unroll
            for (int dx = 0; dx < 3; dx++) {
                unsigned afr[4][4];
#pragma unroll
                for (int mf = 0; mf < 4; mf++) {
                    const int ys = wm * 2 + (mf >> 1) + dy;
                    const int xb = (mf & 1) * 16 + g + dx;
                    afr[mf][0] = sx[t    ][ys][xb];
                    afr[mf][1] = sx[t    ][ys][xb + 8];
                    afr[mf][2] = sx[t + 4][ys][xb];
                    afr[mf][3] = sx[t + 4][ys][xb + 8];
                }
                const int krow0 = t * 9 + dy * 3 + dx;
                const int krow1 = (t + 4) * 9 + dy * 3 + dx;
                unsigned bfr[8][2];
#pragma unroll
                for (int nf = 0; nf < 8; nf++) {
                    bfr[nf][0] = sw[krow0][nf * 8 + g];
                    bfr[nf][1] = sw[krow1][nf * 8 + g];
                }
#pragma unroll
                for (int mf = 0; mf < 4; mf++)
#pragma unroll
                    for (int nf = 0; nf < 8; nf++)
                        mma_tf32(acc[mf][nf], afr[mf], bfr[nf]);
            }
        }
        __syncthreads();
    }

    // epilogue
#pragma unroll
    for (int mf = 0; mf < 4; mf++) {
        const int gy = r0 + wm * 2 + (mf >> 1);
        const int gxA = c0col + (mf & 1) * 16 + g;
        const int gxB = gxA + 8;
        const bool okA = gxA < kW, okB = gxB < kW;
#pragma unroll
        for (int nf = 0; nf < 8; nf++) {
            const int o = ob + nf * 8 + 2 * t;
            const float bv0 = bias[o], bv1 = bias[o + 1];
            float v00 = acc[mf][nf][0] + bv0;
            float v01 = acc[mf][nf][1] + bv1;
            float v10 = acc[mf][nf][2] + bv0;
            float v11 = acc[mf][nf][3] + bv1;
            const size_t base0 = ((size_t)(b * OC + o) * kH + gy) * kW;
            const size_t base1 = ((size_t)(b * OC + o + 1) * kH + gy) * kW;
            if (PH == 0) {
                if (okA) {
                    float a0 = 0.5f * v00 * (1.f + erff(v00 * 0.70710678118654752f));
                    float a1 = 0.5f * v01 * (1.f + erff(v01 * 0.70710678118654752f));
                    out[base0 + gxA] = __uint_as_float(f2tf32(a0));
                    out[base1 + gxA] = __uint_as_float(f2tf32(a1));
                }
                if (okB) {
                    float a2 = 0.5f * v10 * (1.f + erff(v10 * 0.70710678118654752f));
                    float a3 = 0.5f * v11 * (1.f + erff(v11 * 0.70710678118654752f));
                    out[base0 + gxB] = __uint_as_float(f2tf32(a2));
                    out[base1 + gxB] = __uint_as_float(f2tf32(a3));
                }
            } else {
                if (okA) {
                    out[base0 + gxA] = v00 + g_x1[base0 + gxA];
                    out[base1 + gxA] = v01 + g_x1[base1 + gxA];
                }
                if (okB) {
                    out[base0 + gxB] = v10 + g_x1[base0 + gxB];
                    out[base1 + gxB] = v11 + g_x1[base1 + gxB];
                }
            }
        }
    }
}

// ---------------- launch -----------------------------------------------------
extern "C" void kernel_launch(void* const* d_in, const int* in_sizes, int n_in,
                              void* d_out, int out_size) {
    (void)in_sizes; (void)n_in; (void)out_size;
    const float* x       = (const float*)d_in[0];
    const float* ln1_g   = (const float*)d_in[1];
    const float* ln1_b   = (const float*)d_in[2];
    const float* qkv_w   = (const float*)d_in[3];
    const float* qkv_b   = (const float*)d_in[4];
    const float* proj_w  = (const float*)d_in[5];
    const float* proj_b  = (const float*)d_in[6];
    const float* ln2_g   = (const float*)d_in[7];
    const float* ln2_b   = (const float*)d_in[8];
    const float* conv1_w = (const float*)d_in[9];
    const float* conv1_b = (const float*)d_in[10];
    const float* conv2_w = (const float*)d_in[11];
    const float* conv2_b = (const float*)d_in[12];
    float* out = (float*)d_out;

    constexpr int kConvSmem = (2880 * 2 + 5184 * 2) * 4;   // 64512 B
    static bool attr_done = false;
    if (!attr_done) {
        cudaFuncSetAttribute(conv3x3_mma_kernel<0>, cudaFuncAttributeMaxDynamicSharedMemorySize, kConvSmem);
        cudaFuncSetAttribute(conv3x3_mma_kernel<1>, cudaFuncAttributeMaxDynamicSharedMemorySize, kConvSmem);
        attr_done = true;
    }

    wtrans_kernel<0><<<(kHid * kC * 9 + 255) / 256, 256>>>(conv1_w);
    wtrans_kernel<1><<<(kC * kHid * 9 + 255) / 256, 256>>>(conv2_w);

    ln_kernel<0><<<kNT / 256, 256>>>(x, ln1_g, ln1_b);
    gemm_mma_kernel<0><<<dim3(kNT / 256, 9), 128>>>(qkv_w, qkv_b, nullptr);
    attn_kernel<<<kNWin * kHeads, 64>>>();
    gemm_mma_kernel<1><<<dim3(kNT / 256, 3), 128>>>(proj_w, proj_b, x);
    ln_kernel<1><<<kNT / 256, 256>>>(nullptr, ln2_g, ln2_b);
    conv3x3_mma_kernel<0><<<dim3(14, kHid / 64, kB), 128, kConvSmem>>>(conv1_b, nullptr);
    conv3x3_mma_kernel<1><<<dim3(14, kC / 64, kB), 128, kConvSmem>>>(conv2_b, out);
}